// round 4
// baseline (speedup 1.0000x reference)
#include <cuda_runtime.h>

#define DFEAT 128
#define BM 128
#define BK 16
#define ASR 132   // padded A-tile stride (floats); 132*4=528 bytes (16B multiple)

// ---- persistent device scratch (allocation-free rule) ----
__device__ float g_sum[DFEAT];
__device__ float g_sq[DFEAT];
__device__ float g_scale[DFEAT];
__device__ float g_shift[DFEAT];
__device__ int   g_idx_is64;

// ---- packed f32x2 helpers (Blackwell FFMA2; only reachable via inline PTX) ----
#define FMA2(d, a, b) \
    asm("fma.rn.f32x2 %0, %1, %2, %0;" : "+l"(d) : "l"(a), "l"(b))

#define DUP2(d, f) do { \
    unsigned _u = __float_as_uint(f); \
    asm("mov.b64 %0, {%1, %1};" : "=l"(d) : "r"(_u)); \
} while (0)

#define UNPACK2(lo, hi, d) \
    asm("mov.b64 {%0, %1}, %2;" : "=r"(lo), "=r"(hi) : "l"(d))

// ============================================================================
// K0: detect edge-index dtype (int32 vs int64), deterministic.
// If genuinely int64, every value lies in [0, N). If int32 data is read as
// int64, adjacent pairs fuse into huge values -> detected.
// ============================================================================
__global__ void detect_kernel(const long long* __restrict__ ei, int E, int Nnodes)
{
    bool is64 = true;
    int n = 2 * E < 64 ? 2 * E : 64;
    for (int i = 0; i < n; i++) {
        long long v = ei[i];
        if (v < 0 || v >= (long long)Nnodes) { is64 = false; break; }
    }
    g_idx_is64 = is64 ? 1 : 0;
}

// ============================================================================
// K1: out = (1+eps) * x   (and reset BN stat accumulators)
// ============================================================================
__global__ void init_kernel(const float4* __restrict__ x,
                            float4* __restrict__ out,
                            const float* __restrict__ eps,
                            long total4)
{
    if (blockIdx.x == 0 && threadIdx.x < DFEAT) {
        g_sum[threadIdx.x] = 0.f;
        g_sq[threadIdx.x]  = 0.f;
    }
    float c = 1.0f + *eps;
    long i = (long)blockIdx.x * blockDim.x + threadIdx.x;
    long stride = (long)gridDim.x * blockDim.x;
    for (; i < total4; i += stride) {
        float4 v = x[i];
        v.x *= c; v.y *= c; v.z *= c; v.w *= c;
        out[i] = v;
    }
}

// ============================================================================
// K2: scatter-add  out[dst] += x[src]   (warp per edge, float4 vector atomics)
// Dtype chosen by g_idx_is64 (uniform branch). Bounds-clamped for safety.
// ============================================================================
__global__ void scatter_kernel(const float4* __restrict__ x,
                               const void* __restrict__ ei_raw,
                               float4* __restrict__ out,
                               int E, int Nnodes)
{
    int e = blockIdx.x * 8 + (threadIdx.x >> 5);
    if (e >= E) return;
    int lane = threadIdx.x & 31;

    unsigned long long s, d;
    if (g_idx_is64) {
        const long long* ei = (const long long*)ei_raw;
        s = (unsigned long long)ei[e];
        d = (unsigned long long)ei[E + e];
    } else {
        const int* ei = (const int*)ei_raw;
        s = (unsigned long long)(unsigned)ei[e];
        d = (unsigned long long)(unsigned)ei[E + e];
    }
    if (s >= (unsigned long long)Nnodes || d >= (unsigned long long)Nnodes) return;
    float4 v = x[s * 32 + lane];
    atomicAdd(&out[d * 32 + lane], v);   // sm_90+ vector red
}

// ============================================================================
// K3/K5: in-place tiled GEMM, C[M,128] = f(C) @ W + bias
//   PHASE 1: f = identity; epilogue accumulates per-column sum/sumsq (BN stats)
//   PHASE 2: f = ReLU(BN(.)) via precomputed g_scale/g_shift applied at A-load
// Each block owns rows [m0, m0+128) exclusively -> in-place is safe.
// ============================================================================
template <int PHASE>
__global__ __launch_bounds__(256, 2)
void gemm_kernel(float* __restrict__ C,
                 const float* __restrict__ W,
                 const float* __restrict__ bias,
                 int M)
{
    __shared__ float As[BK * ASR];
    __shared__ float Bs[BK * DFEAT];
    __shared__ float s_scale[DFEAT];
    __shared__ float s_shift[DFEAT];
    __shared__ float s_sum[DFEAT];
    __shared__ float s_sq[DFEAT];

    const int t  = threadIdx.x;
    const int m0 = blockIdx.x * BM;
    const int tx = t & 15;   // n-group: columns tx*8 .. tx*8+7
    const int ty = t >> 4;   // m-group: rows    ty*8 .. ty*8+7

    if (PHASE == 2) {
        if (t < DFEAT) { s_scale[t] = g_scale[t]; s_shift[t] = g_shift[t]; }
    } else {
        if (t < DFEAT) { s_sum[t] = 0.f; s_sq[t] = 0.f; }
    }
    __syncthreads();

    unsigned long long acc[8][4];
#pragma unroll
    for (int i = 0; i < 8; i++)
#pragma unroll
        for (int j = 0; j < 4; j++) acc[i][j] = 0ULL;

    for (int k0 = 0; k0 < DFEAT; k0 += BK) {
        // ---- load A chunk (rows m0..m0+127, cols k0..k0+15), transpose to As[k][m]
#pragma unroll
        for (int r = 0; r < 2; r++) {
            int id  = r * 256 + t;
            int ml  = id >> 2;        // local row 0..127
            int kk4 = id & 3;         // which float4 within the 16-wide k chunk
            int m   = m0 + ml;
            float4 v = make_float4(0.f, 0.f, 0.f, 0.f);
            if (m < M)
                v = *reinterpret_cast<const float4*>(C + (long)m * DFEAT + k0 + kk4 * 4);
            if (PHASE == 2) {
                int kb = k0 + kk4 * 4;
                v.x = fmaxf(v.x * s_scale[kb + 0] + s_shift[kb + 0], 0.f);
                v.y = fmaxf(v.y * s_scale[kb + 1] + s_shift[kb + 1], 0.f);
                v.z = fmaxf(v.z * s_scale[kb + 2] + s_shift[kb + 2], 0.f);
                v.w = fmaxf(v.w * s_scale[kb + 3] + s_shift[kb + 3], 0.f);
            }
            As[(kk4 * 4 + 0) * ASR + ml] = v.x;
            As[(kk4 * 4 + 1) * ASR + ml] = v.y;
            As[(kk4 * 4 + 2) * ASR + ml] = v.z;
            As[(kk4 * 4 + 3) * ASR + ml] = v.w;
        }
        // ---- load B chunk (W[k0..k0+15][0..127]) straight copy
#pragma unroll
        for (int r = 0; r < 2; r++) {
            int id = r * 256 + t;
            int kk = id >> 5;
            int n4 = id & 31;
            *reinterpret_cast<float4*>(&Bs[kk * DFEAT + n4 * 4]) =
                *reinterpret_cast<const float4*>(W + (long)(k0 + kk) * DFEAT + n4 * 4);
        }
        __syncthreads();

        // ---- compute: 8x8 per thread, packed f32x2 along n
#pragma unroll
        for (int kk = 0; kk < BK; kk++) {
            const float* ar = &As[kk * ASR + ty * 8];
            float4 a0 = *reinterpret_cast<const float4*>(ar);
            float4 a1 = *reinterpret_cast<const float4*>(ar + 4);
            unsigned long long ad[8];
            DUP2(ad[0], a0.x); DUP2(ad[1], a0.y); DUP2(ad[2], a0.z); DUP2(ad[3], a0.w);
            DUP2(ad[4], a1.x); DUP2(ad[5], a1.y); DUP2(ad[6], a1.z); DUP2(ad[7], a1.w);

            const ulonglong2* bp =
                reinterpret_cast<const ulonglong2*>(&Bs[kk * DFEAT + tx * 8]);
            ulonglong2 b01 = bp[0];
            ulonglong2 b23 = bp[1];
            unsigned long long bq0 = b01.x, bq1 = b01.y, bq2 = b23.x, bq3 = b23.y;

#pragma unroll
            for (int i = 0; i < 8; i++) {
                FMA2(acc[i][0], ad[i], bq0);
                FMA2(acc[i][1], ad[i], bq1);
                FMA2(acc[i][2], ad[i], bq2);
                FMA2(acc[i][3], ad[i], bq3);
            }
        }
        __syncthreads();
    }

    // ---- epilogue
    float bv[8];
#pragma unroll
    for (int j = 0; j < 8; j++) bv[j] = bias[tx * 8 + j];

    float csum[8], csq[8];
#pragma unroll
    for (int j = 0; j < 8; j++) { csum[j] = 0.f; csq[j] = 0.f; }

#pragma unroll
    for (int i = 0; i < 8; i++) {
        int m = m0 + ty * 8 + i;
        if (m < M) {
            float v[8];
#pragma unroll
            for (int j2 = 0; j2 < 4; j2++) {
                unsigned lo, hi;
                UNPACK2(lo, hi, acc[i][j2]);
                v[2 * j2]     = __uint_as_float(lo) + bv[2 * j2];
                v[2 * j2 + 1] = __uint_as_float(hi) + bv[2 * j2 + 1];
            }
            if (PHASE == 1) {
#pragma unroll
                for (int j = 0; j < 8; j++) {
                    csum[j] += v[j];
                    csq[j]  += v[j] * v[j];
                }
            }
            float4 o0 = make_float4(v[0], v[1], v[2], v[3]);
            float4 o1 = make_float4(v[4], v[5], v[6], v[7]);
            *reinterpret_cast<float4*>(C + (long)m * DFEAT + tx * 8)     = o0;
            *reinterpret_cast<float4*>(C + (long)m * DFEAT + tx * 8 + 4) = o1;
        }
    }

    if (PHASE == 1) {
#pragma unroll
        for (int j = 0; j < 8; j++) {
            atomicAdd(&s_sum[tx * 8 + j], csum[j]);
            atomicAdd(&s_sq[tx * 8 + j],  csq[j]);
        }
        __syncthreads();
        if (t < DFEAT) {
            atomicAdd(&g_sum[t], s_sum[t]);
            atomicAdd(&g_sq[t],  s_sq[t]);
        }
    }
}

// ============================================================================
// K4: fold BN stats into affine scale/shift:  y = h*scale + shift, then ReLU
// ============================================================================
__global__ void finalize_kernel(const float* __restrict__ gamma,
                                const float* __restrict__ beta,
                                float invM)
{
    int t = threadIdx.x;
    float mu   = g_sum[t] * invM;
    float var  = g_sq[t] * invM - mu * mu;
    float rstd = rsqrtf(var + 1e-5f);
    float sc   = rstd * gamma[t];
    g_scale[t] = sc;
    g_shift[t] = beta[t] - mu * sc;
}

// ============================================================================
// launch: resolve inputs by size signature (robust to metadata ordering)
// ============================================================================
extern "C" void kernel_launch(void* const* d_in, const int* in_sizes, int n_in,
                              void* d_out, int out_size)
{
    // Classify inputs by element count:
    //   x:12.8M  edge_index:1.28M(=2E)  W1,W2:16384  b1,gamma,beta,b2:128  eps:1
    int ix = -1, ie = -1, iW1 = -1, iW2 = -1, ieps = -1;
    int v128[8]; int n128 = 0;
    long best_x = -1, best_e = -1;
    for (int i = 0; i < n_in; i++) {
        long sz = in_sizes[i];
        if (sz > best_x) {
            best_e = best_x; ie = ix;
            best_x = sz; ix = i;
        } else if (sz > best_e) { best_e = sz; ie = i; }
    }
    for (int i = 0; i < n_in; i++) {
        if (i == ix || i == ie) continue;
        long sz = in_sizes[i];
        if (sz == DFEAT * DFEAT) { if (iW1 < 0) iW1 = i; else iW2 = i; }
        else if (sz == DFEAT)    { if (n128 < 8) v128[n128++] = i; }
        else                     { ieps = i; }   // scalar
    }
    // 128-vector roles:
    //   dict order  (x first):  b1, gamma, beta, b2
    //   alpha order (x last):   b1, b2, beta, gamma
    int ib1, igamma, ibeta, ib2;
    if (ix == 0) { ib1 = v128[0]; igamma = v128[1]; ibeta = v128[2]; ib2 = v128[3]; }
    else         { ib1 = v128[0]; ib2 = v128[1];    ibeta = v128[2]; igamma = v128[3]; }

    const float* x     = (const float*)d_in[ix];
    const void*  ei    = d_in[ie];
    const float* W1    = (const float*)d_in[iW1];
    const float* b1    = (const float*)d_in[ib1];
    const float* gamma = (const float*)d_in[igamma];
    const float* beta  = (const float*)d_in[ibeta];
    const float* W2    = (const float*)d_in[iW2];
    const float* b2    = (const float*)d_in[ib2];
    const float* eps   = (const float*)d_in[ieps];
    float*       out   = (float*)d_out;

    int M = in_sizes[ix] / DFEAT;
    int E = in_sizes[ie] / 2;
    long total4 = (long)M * (DFEAT / 4);

    // K0: detect edge-index dtype
    detect_kernel<<<1, 1>>>((const long long*)ei, E, M);

    // K1: out = (1+eps)*x ; zero stat accumulators
    init_kernel<<<2048, 256>>>((const float4*)x, (float4*)out, eps, total4);

    // K2: out[dst] += x[src]  (GIN sum aggregation)
    scatter_kernel<<<(E + 7) / 8, 256>>>((const float4*)x, ei, (float4*)out, E, M);

    int gblocks = (M + BM - 1) / BM;

    // K3: out = out @ W1 + b1 (in place), BN stats accumulated
    gemm_kernel<1><<<gblocks, 256>>>(out, W1, b1, M);

    // K4: fold mean/var/gamma/beta into scale/shift
    finalize_kernel<<<1, DFEAT>>>(gamma, beta, 1.0f / (float)M);

    // K5: out = ReLU(BN(out)) @ W2 + b2 (in place)
    gemm_kernel<2><<<gblocks, 256>>>(out, W2, b2, M);
}

// round 5
// speedup vs baseline: 1.0904x; 1.0904x over previous
#include <cuda_runtime.h>

#define DFEAT 128
#define BM 128
#define SA 132   // A smem stride in words (≡4 mod 32 -> conflict-free A frags)
#define SB 136   // B smem stride in words (≡8 mod 32 -> conflict-free B frags)

// ---- persistent device scratch (allocation-free rule) ----
__device__ float g_sum[DFEAT];
__device__ float g_sq[DFEAT];
__device__ float g_scale[DFEAT];
__device__ float g_shift[DFEAT];
__device__ int   g_idx_is64;

__device__ __forceinline__ unsigned f2tf32(float f) {
    unsigned u;
    asm("cvt.rna.tf32.f32 %0, %1;" : "=r"(u) : "f"(f));
    return u;
}

#define MMA_TF32(d, a, b) \
    asm volatile("mma.sync.aligned.m16n8k8.row.col.f32.tf32.tf32.f32 " \
        "{%0,%1,%2,%3}, {%4,%5,%6,%7}, {%8,%9}, {%0,%1,%2,%3};" \
        : "+f"((d)[0]), "+f"((d)[1]), "+f"((d)[2]), "+f"((d)[3]) \
        : "r"((a)[0]), "r"((a)[1]), "r"((a)[2]), "r"((a)[3]), \
          "r"((b)[0]), "r"((b)[1]))

// ============================================================================
// K0: detect edge-index dtype (int32 vs int64), deterministic.
// ============================================================================
__global__ void detect_kernel(const long long* __restrict__ ei, int E, int Nnodes)
{
    bool is64 = true;
    int n = 2 * E < 64 ? 2 * E : 64;
    for (int i = 0; i < n; i++) {
        long long v = ei[i];
        if (v < 0 || v >= (long long)Nnodes) { is64 = false; break; }
    }
    g_idx_is64 = is64 ? 1 : 0;
}

// ============================================================================
// K1: out = (1+eps) * x   (and reset BN stat accumulators)
// ============================================================================
__global__ void init_kernel(const float4* __restrict__ x,
                            float4* __restrict__ out,
                            const float* __restrict__ eps,
                            long total4)
{
    if (blockIdx.x == 0 && threadIdx.x < DFEAT) {
        g_sum[threadIdx.x] = 0.f;
        g_sq[threadIdx.x]  = 0.f;
    }
    float c = 1.0f + *eps;
    long i = (long)blockIdx.x * blockDim.x + threadIdx.x;
    long stride = (long)gridDim.x * blockDim.x;
    for (; i < total4; i += stride) {
        float4 v = x[i];
        v.x *= c; v.y *= c; v.z *= c; v.w *= c;
        out[i] = v;
    }
}

// ============================================================================
// K2: scatter-add  out[dst] += x[src]   (warp per edge, float4 vector atomics)
// ============================================================================
__global__ void scatter_kernel(const float4* __restrict__ x,
                               const void* __restrict__ ei_raw,
                               float4* __restrict__ out,
                               int E, int Nnodes)
{
    int e = blockIdx.x * 8 + (threadIdx.x >> 5);
    if (e >= E) return;
    int lane = threadIdx.x & 31;

    unsigned long long s, d;
    if (g_idx_is64) {
        const long long* ei = (const long long*)ei_raw;
        s = (unsigned long long)ei[e];
        d = (unsigned long long)ei[E + e];
    } else {
        const int* ei = (const int*)ei_raw;
        s = (unsigned long long)(unsigned)ei[e];
        d = (unsigned long long)(unsigned)ei[E + e];
    }
    if (s >= (unsigned long long)Nnodes || d >= (unsigned long long)Nnodes) return;
    float4 v = x[s * 32 + lane];
    atomicAdd(&out[d * 32 + lane], v);   // sm_90+ vector red
}

// ============================================================================
// K3/K5: in-place GEMM via mma.sync tf32.  C[M,128] = f(C) @ W + bias
//   PHASE 1: f = identity; epilogue accumulates per-column sum/sumsq
//   PHASE 2: f = ReLU(BN(.)) applied at A-load via g_scale/g_shift
// One CTA = 128 rows, full K=128, full N=128. 8 warps: 4(m) x 2(n),
// each warp 32 rows x 64 cols = 2x8 tiles of m16n8k8.
// ============================================================================
template <int PHASE>
__global__ __launch_bounds__(256, 1)
void gemm_tc_kernel(float* __restrict__ C,
                    const float* __restrict__ W,
                    const float* __restrict__ bias,
                    int M)
{
    extern __shared__ unsigned smem_u[];
    unsigned* As = smem_u;                 // [128][SA]
    unsigned* Bs = smem_u + 128 * SA;      // [128][SB]
    __shared__ float s_scale[DFEAT];
    __shared__ float s_shift[DFEAT];
    __shared__ float s_sum[DFEAT];
    __shared__ float s_sq[DFEAT];

    const int t  = threadIdx.x;
    const int m0 = blockIdx.x * BM;

    if (PHASE == 2) {
        if (t < DFEAT) { s_scale[t] = g_scale[t]; s_shift[t] = g_shift[t]; }
    } else {
        if (t < DFEAT) { s_sum[t] = 0.f; s_sq[t] = 0.f; }
    }
    __syncthreads();

    // ---- load A tile (rows m0..m0+127, all 128 cols), tf32-convert ----
#pragma unroll
    for (int i = 0; i < 16; i++) {
        int idx = i * 256 + t;          // float4 index, 0..4095
        int row = idx >> 5;             // 32 float4 per row
        int c4  = idx & 31;
        float4 v = make_float4(0.f, 0.f, 0.f, 0.f);
        int m = m0 + row;
        if (m < M)
            v = *reinterpret_cast<const float4*>(C + (long)m * DFEAT + c4 * 4);
        if (PHASE == 2) {
            int kb = c4 * 4;
            v.x = fmaxf(fmaf(v.x, s_scale[kb + 0], s_shift[kb + 0]), 0.f);
            v.y = fmaxf(fmaf(v.y, s_scale[kb + 1], s_shift[kb + 1]), 0.f);
            v.z = fmaxf(fmaf(v.z, s_scale[kb + 2], s_shift[kb + 2]), 0.f);
            v.w = fmaxf(fmaf(v.w, s_scale[kb + 3], s_shift[kb + 3]), 0.f);
        }
        uint4 u = make_uint4(f2tf32(v.x), f2tf32(v.y), f2tf32(v.z), f2tf32(v.w));
        *reinterpret_cast<uint4*>(As + row * SA + c4 * 4) = u;
    }
    // ---- load B tile (W[128][128]), tf32-convert ----
#pragma unroll
    for (int i = 0; i < 16; i++) {
        int idx = i * 256 + t;
        int k   = idx >> 5;
        int c4  = idx & 31;
        float4 v = *reinterpret_cast<const float4*>(W + (long)k * DFEAT + c4 * 4);
        uint4 u = make_uint4(f2tf32(v.x), f2tf32(v.y), f2tf32(v.z), f2tf32(v.w));
        *reinterpret_cast<uint4*>(Bs + k * SB + c4 * 4) = u;
    }
    __syncthreads();

    const int lane = t & 31;
    const int warp = t >> 5;
    const int wm = warp >> 1;      // 0..3
    const int wn = warp & 1;       // 0..1
    const int q  = lane & 3;       // 0..3
    const int rg = lane >> 2;      // 0..7

    float acc[2][8][4];
#pragma unroll
    for (int mt = 0; mt < 2; mt++)
#pragma unroll
        for (int nt = 0; nt < 8; nt++)
#pragma unroll
            for (int j = 0; j < 4; j++) acc[mt][nt][j] = 0.f;

#pragma unroll 2
    for (int k0 = 0; k0 < DFEAT; k0 += 8) {
        unsigned a[2][4];
#pragma unroll
        for (int mt = 0; mt < 2; mt++) {
            const unsigned* p = As + (wm * 32 + mt * 16 + rg) * SA + k0 + q;
            a[mt][0] = p[0];
            a[mt][1] = p[8 * SA];
            a[mt][2] = p[4];
            a[mt][3] = p[8 * SA + 4];
        }
        unsigned b[8][2];
#pragma unroll
        for (int nt = 0; nt < 8; nt++) {
            const unsigned* p = Bs + (k0 + q) * SB + wn * 64 + nt * 8 + rg;
            b[nt][0] = p[0];
            b[nt][1] = p[4 * SB];
        }
#pragma unroll
        for (int mt = 0; mt < 2; mt++)
#pragma unroll
            for (int nt = 0; nt < 8; nt++)
                MMA_TF32(acc[mt][nt], a[mt], b[nt]);
    }

    // ---- epilogue: bias add, in-place store, BN stats (PHASE 1) ----
    float bv[8][2];
#pragma unroll
    for (int nt = 0; nt < 8; nt++) {
        int col = wn * 64 + nt * 8 + 2 * q;
        bv[nt][0] = bias[col];
        bv[nt][1] = bias[col + 1];
    }

    float csum[8][2], csq[8][2];
#pragma unroll
    for (int nt = 0; nt < 8; nt++) {
        csum[nt][0] = csum[nt][1] = 0.f;
        csq[nt][0]  = csq[nt][1]  = 0.f;
    }

#pragma unroll
    for (int mt = 0; mt < 2; mt++) {
        int r0 = m0 + wm * 32 + mt * 16 + rg;
        int r1 = r0 + 8;
#pragma unroll
        for (int nt = 0; nt < 8; nt++) {
            int col = wn * 64 + nt * 8 + 2 * q;
            float v0 = acc[mt][nt][0] + bv[nt][0];
            float v1 = acc[mt][nt][1] + bv[nt][1];
            float v2 = acc[mt][nt][2] + bv[nt][0];
            float v3 = acc[mt][nt][3] + bv[nt][1];
            if (r0 < M) {
                *reinterpret_cast<float2*>(C + (long)r0 * DFEAT + col) =
                    make_float2(v0, v1);
                if (PHASE == 1) {
                    csum[nt][0] += v0; csq[nt][0] += v0 * v0;
                    csum[nt][1] += v1; csq[nt][1] += v1 * v1;
                }
            }
            if (r1 < M) {
                *reinterpret_cast<float2*>(C + (long)r1 * DFEAT + col) =
                    make_float2(v2, v3);
                if (PHASE == 1) {
                    csum[nt][0] += v2; csq[nt][0] += v2 * v2;
                    csum[nt][1] += v3; csq[nt][1] += v3 * v3;
                }
            }
        }
    }

    if (PHASE == 1) {
        // reduce over the 8 row-groups within the warp (lanes differing in rg)
#pragma unroll
        for (int nt = 0; nt < 8; nt++)
#pragma unroll
            for (int j = 0; j < 2; j++) {
#pragma unroll
                for (int ofs = 4; ofs < 32; ofs <<= 1) {
                    csum[nt][j] += __shfl_xor_sync(0xffffffffu, csum[nt][j], ofs);
                    csq[nt][j]  += __shfl_xor_sync(0xffffffffu, csq[nt][j],  ofs);
                }
            }
        if (rg == 0) {   // lanes 0..3 hold column totals
#pragma unroll
            for (int nt = 0; nt < 8; nt++) {
                int col = wn * 64 + nt * 8 + 2 * q;
                atomicAdd(&s_sum[col],     csum[nt][0]);
                atomicAdd(&s_sum[col + 1], csum[nt][1]);
                atomicAdd(&s_sq[col],      csq[nt][0]);
                atomicAdd(&s_sq[col + 1],  csq[nt][1]);
            }
        }
        __syncthreads();
        if (t < DFEAT) {
            atomicAdd(&g_sum[t], s_sum[t]);
            atomicAdd(&g_sq[t],  s_sq[t]);
        }
    }
}

// ============================================================================
// K4: fold BN stats into affine scale/shift
// ============================================================================
__global__ void finalize_kernel(const float* __restrict__ gamma,
                                const float* __restrict__ beta,
                                float invM)
{
    int t = threadIdx.x;
    float mu   = g_sum[t] * invM;
    float var  = g_sq[t] * invM - mu * mu;
    float rstd = rsqrtf(var + 1e-5f);
    float sc   = rstd * gamma[t];
    g_scale[t] = sc;
    g_shift[t] = beta[t] - mu * sc;
}

// ============================================================================
// launch: resolve inputs by size signature (robust to metadata ordering)
// ============================================================================
extern "C" void kernel_launch(void* const* d_in, const int* in_sizes, int n_in,
                              void* d_out, int out_size)
{
    int ix = -1, ie = -1, iW1 = -1, iW2 = -1, ieps = -1;
    int v128[8]; int n128 = 0;
    long best_x = -1, best_e = -1;
    for (int i = 0; i < n_in; i++) {
        long sz = in_sizes[i];
        if (sz > best_x) {
            best_e = best_x; ie = ix;
            best_x = sz; ix = i;
        } else if (sz > best_e) { best_e = sz; ie = i; }
    }
    for (int i = 0; i < n_in; i++) {
        if (i == ix || i == ie) continue;
        long sz = in_sizes[i];
        if (sz == DFEAT * DFEAT) { if (iW1 < 0) iW1 = i; else iW2 = i; }
        else if (sz == DFEAT)    { if (n128 < 8) v128[n128++] = i; }
        else                     { ieps = i; }
    }
    int ib1, igamma, ibeta, ib2;
    if (ix == 0) { ib1 = v128[0]; igamma = v128[1]; ibeta = v128[2]; ib2 = v128[3]; }
    else         { ib1 = v128[0]; ib2 = v128[1];    ibeta = v128[2]; igamma = v128[3]; }

    const float* x     = (const float*)d_in[ix];
    const void*  ei    = d_in[ie];
    const float* W1    = (const float*)d_in[iW1];
    const float* b1    = (const float*)d_in[ib1];
    const float* gamma = (const float*)d_in[igamma];
    const float* beta  = (const float*)d_in[ibeta];
    const float* W2    = (const float*)d_in[iW2];
    const float* b2    = (const float*)d_in[ib2];
    const float* eps   = (const float*)d_in[ieps];
    float*       out   = (float*)d_out;

    int M = in_sizes[ix] / DFEAT;
    int E = in_sizes[ie] / 2;
    long total4 = (long)M * (DFEAT / 4);

    static int smem_set = 0;
    const int dyn_smem = (128 * SA + 128 * SB) * 4;   // 137216 bytes
    if (!smem_set) {
        cudaFuncSetAttribute(gemm_tc_kernel<1>,
                             cudaFuncAttributeMaxDynamicSharedMemorySize, dyn_smem);
        cudaFuncSetAttribute(gemm_tc_kernel<2>,
                             cudaFuncAttributeMaxDynamicSharedMemorySize, dyn_smem);
        smem_set = 1;
    }

    // K0: detect edge-index dtype
    detect_kernel<<<1, 1>>>((const long long*)ei, E, M);

    // K1: out = (1+eps)*x ; zero stat accumulators
    init_kernel<<<2048, 256>>>((const float4*)x, (float4*)out, eps, total4);

    // K2: out[dst] += x[src]  (GIN sum aggregation)
    scatter_kernel<<<(E + 7) / 8, 256>>>((const float4*)x, ei, (float4*)out, E, M);

    int gblocks = (M + BM - 1) / BM;

    // K3: out = out @ W1 + b1 (in place), BN stats accumulated
    gemm_tc_kernel<1><<<gblocks, 256, dyn_smem>>>(out, W1, b1, M);

    // K4: fold mean/var/gamma/beta into scale/shift
    finalize_kernel<<<1, DFEAT>>>(gamma, beta, 1.0f / (float)M);

    // K5: out = ReLU(BN(out)) @ W2 + b2 (in place)
    gemm_tc_kernel<2><<<gblocks, 256, dyn_smem>>>(out, W2, b2, M);
}

// round 6
// speedup vs baseline: 1.5836x; 1.4523x over previous
#include <cuda_runtime.h>

#define DFEAT 128
#define BM 64
#define SA 132   // A smem stride in words (≡4 mod 32 -> conflict-free A frags)
#define SB 136   // B smem stride in words (≡8 mod 32 -> conflict-free B frags)

// ---- persistent device scratch (allocation-free rule) ----
__device__ float g_sum[DFEAT];
__device__ float g_sq[DFEAT];
__device__ float g_scale[DFEAT];
__device__ float g_shift[DFEAT];
__device__ int   g_idx_is64;

__device__ __forceinline__ unsigned f2tf32(float f) {
    unsigned u;
    asm("cvt.rna.tf32.f32 %0, %1;" : "=r"(u) : "f"(f));
    return u;
}

#define MMA_TF32(d, a, b) \
    asm volatile("mma.sync.aligned.m16n8k8.row.col.f32.tf32.tf32.f32 " \
        "{%0,%1,%2,%3}, {%4,%5,%6,%7}, {%8,%9}, {%0,%1,%2,%3};" \
        : "+f"((d)[0]), "+f"((d)[1]), "+f"((d)[2]), "+f"((d)[3]) \
        : "r"((a)[0]), "r"((a)[1]), "r"((a)[2]), "r"((a)[3]), \
          "r"((b)[0]), "r"((b)[1]))

// ============================================================================
// K0: detect edge-index dtype (int32 vs int64), deterministic.
// ============================================================================
__global__ void detect_kernel(const long long* __restrict__ ei, int E, int Nnodes)
{
    bool is64 = true;
    int n = 2 * E < 64 ? 2 * E : 64;
    for (int i = 0; i < n; i++) {
        long long v = ei[i];
        if (v < 0 || v >= (long long)Nnodes) { is64 = false; break; }
    }
    g_idx_is64 = is64 ? 1 : 0;
}

// ============================================================================
// K1: out = (1+eps) * x   (and reset BN stat accumulators)
// ============================================================================
__global__ void init_kernel(const float4* __restrict__ x,
                            float4* __restrict__ out,
                            const float* __restrict__ eps,
                            long total4)
{
    if (blockIdx.x == 0 && threadIdx.x < DFEAT) {
        g_sum[threadIdx.x] = 0.f;
        g_sq[threadIdx.x]  = 0.f;
    }
    float c = 1.0f + *eps;
    long i = (long)blockIdx.x * blockDim.x + threadIdx.x;
    long stride = (long)gridDim.x * blockDim.x;
    for (; i < total4; i += stride) {
        float4 v = x[i];
        v.x *= c; v.y *= c; v.z *= c; v.w *= c;
        out[i] = v;
    }
}

// ============================================================================
// K2: scatter-add  out[dst] += x[src]   (warp per edge, float4 vector atomics)
// ============================================================================
__global__ void scatter_kernel(const float4* __restrict__ x,
                               const void* __restrict__ ei_raw,
                               float4* __restrict__ out,
                               int E, int Nnodes)
{
    int e = blockIdx.x * 8 + (threadIdx.x >> 5);
    if (e >= E) return;
    int lane = threadIdx.x & 31;

    unsigned long long s, d;
    if (g_idx_is64) {
        const long long* ei = (const long long*)ei_raw;
        s = (unsigned long long)ei[e];
        d = (unsigned long long)ei[E + e];
    } else {
        const int* ei = (const int*)ei_raw;
        s = (unsigned long long)(unsigned)ei[e];
        d = (unsigned long long)(unsigned)ei[E + e];
    }
    if (s >= (unsigned long long)Nnodes || d >= (unsigned long long)Nnodes) return;
    float4 v = x[s * 32 + lane];
    atomicAdd(&out[d * 32 + lane], v);   // sm_90+ vector red
}

// ============================================================================
// K3/K5: in-place GEMM via mma.sync tf32.  C[M,128] = f(C) @ W + bias
//   PHASE 1: f = identity; epilogue accumulates per-column sum/sumsq
//   PHASE 2: f = ReLU(BN(.)) applied at A-load via g_scale/g_shift
// One CTA = 64 rows (BM=64), full K=128, full N=128. 103 KB smem -> 2 CTA/SM.
// 8 warps: 2(m) x 4(n); warp tile 32 rows x 32 cols = 2x4 m16n8k8 tiles.
// ============================================================================
template <int PHASE>
__global__ __launch_bounds__(256)
void gemm_tc_kernel(float* __restrict__ C,
                    const float* __restrict__ W,
                    const float* __restrict__ bias,
                    int M)
{
    extern __shared__ unsigned smem_u[];
    unsigned* As = smem_u;                // [64][SA]
    unsigned* Bs = smem_u + BM * SA;      // [128][SB]
    __shared__ float s_scale[DFEAT];
    __shared__ float s_shift[DFEAT];
    __shared__ float s_sum[DFEAT];
    __shared__ float s_sq[DFEAT];

    const int t  = threadIdx.x;
    const int m0 = blockIdx.x * BM;

    if (PHASE == 2) {
        if (t < DFEAT) { s_scale[t] = g_scale[t]; s_shift[t] = g_shift[t]; }
    } else {
        if (t < DFEAT) { s_sum[t] = 0.f; s_sq[t] = 0.f; }
    }
    __syncthreads();

    // ---- load A tile (rows m0..m0+63, all 128 cols), tf32-convert ----
#pragma unroll
    for (int i = 0; i < 8; i++) {
        int idx = i * 256 + t;          // float4 index, 0..2047
        int row = idx >> 5;             // 32 float4 per row
        int c4  = idx & 31;
        float4 v = make_float4(0.f, 0.f, 0.f, 0.f);
        int m = m0 + row;
        if (m < M)
            v = *reinterpret_cast<const float4*>(C + (long)m * DFEAT + c4 * 4);
        if (PHASE == 2) {
            int kb = c4 * 4;
            v.x = fmaxf(fmaf(v.x, s_scale[kb + 0], s_shift[kb + 0]), 0.f);
            v.y = fmaxf(fmaf(v.y, s_scale[kb + 1], s_shift[kb + 1]), 0.f);
            v.z = fmaxf(fmaf(v.z, s_scale[kb + 2], s_shift[kb + 2]), 0.f);
            v.w = fmaxf(fmaf(v.w, s_scale[kb + 3], s_shift[kb + 3]), 0.f);
        }
        uint4 u = make_uint4(f2tf32(v.x), f2tf32(v.y), f2tf32(v.z), f2tf32(v.w));
        *reinterpret_cast<uint4*>(As + row * SA + c4 * 4) = u;
    }
    // ---- load B tile (W[128][128]), tf32-convert ----
#pragma unroll
    for (int i = 0; i < 16; i++) {
        int idx = i * 256 + t;
        int k   = idx >> 5;
        int c4  = idx & 31;
        float4 v = *reinterpret_cast<const float4*>(W + (long)k * DFEAT + c4 * 4);
        uint4 u = make_uint4(f2tf32(v.x), f2tf32(v.y), f2tf32(v.z), f2tf32(v.w));
        *reinterpret_cast<uint4*>(Bs + k * SB + c4 * 4) = u;
    }
    __syncthreads();

    const int lane = t & 31;
    const int warp = t >> 5;
    const int wm = warp >> 2;      // 0..1
    const int wn = warp & 3;       // 0..3
    const int q  = lane & 3;       // 0..3
    const int rg = lane >> 2;      // 0..7

    float acc[2][4][4];
#pragma unroll
    for (int mt = 0; mt < 2; mt++)
#pragma unroll
        for (int nt = 0; nt < 4; nt++)
#pragma unroll
            for (int j = 0; j < 4; j++) acc[mt][nt][j] = 0.f;

#pragma unroll 4
    for (int k0 = 0; k0 < DFEAT; k0 += 8) {
        unsigned a[2][4];
#pragma unroll
        for (int mt = 0; mt < 2; mt++) {
            const unsigned* p = As + (wm * 32 + mt * 16 + rg) * SA + k0 + q;
            a[mt][0] = p[0];
            a[mt][1] = p[8 * SA];
            a[mt][2] = p[4];
            a[mt][3] = p[8 * SA + 4];
        }
        unsigned b[4][2];
#pragma unroll
        for (int nt = 0; nt < 4; nt++) {
            const unsigned* p = Bs + (k0 + q) * SB + wn * 32 + nt * 8 + rg;
            b[nt][0] = p[0];
            b[nt][1] = p[4 * SB];
        }
#pragma unroll
        for (int mt = 0; mt < 2; mt++)
#pragma unroll
            for (int nt = 0; nt < 4; nt++)
                MMA_TF32(acc[mt][nt], a[mt], b[nt]);
    }

    // ---- epilogue: bias add, in-place store, BN stats (PHASE 1) ----
    float bv[4][2];
#pragma unroll
    for (int nt = 0; nt < 4; nt++) {
        int col = wn * 32 + nt * 8 + 2 * q;
        bv[nt][0] = bias[col];
        bv[nt][1] = bias[col + 1];
    }

    float csum[4][2], csq[4][2];
#pragma unroll
    for (int nt = 0; nt < 4; nt++) {
        csum[nt][0] = csum[nt][1] = 0.f;
        csq[nt][0]  = csq[nt][1]  = 0.f;
    }

#pragma unroll
    for (int mt = 0; mt < 2; mt++) {
        int r0 = m0 + wm * 32 + mt * 16 + rg;
        int r1 = r0 + 8;
#pragma unroll
        for (int nt = 0; nt < 4; nt++) {
            int col = wn * 32 + nt * 8 + 2 * q;
            float v0 = acc[mt][nt][0] + bv[nt][0];
            float v1 = acc[mt][nt][1] + bv[nt][1];
            float v2 = acc[mt][nt][2] + bv[nt][0];
            float v3 = acc[mt][nt][3] + bv[nt][1];
            if (r0 < M) {
                *reinterpret_cast<float2*>(C + (long)r0 * DFEAT + col) =
                    make_float2(v0, v1);
                if (PHASE == 1) {
                    csum[nt][0] += v0; csq[nt][0] += v0 * v0;
                    csum[nt][1] += v1; csq[nt][1] += v1 * v1;
                }
            }
            if (r1 < M) {
                *reinterpret_cast<float2*>(C + (long)r1 * DFEAT + col) =
                    make_float2(v2, v3);
                if (PHASE == 1) {
                    csum[nt][0] += v2; csq[nt][0] += v2 * v2;
                    csum[nt][1] += v3; csq[nt][1] += v3 * v3;
                }
            }
        }
    }

    if (PHASE == 1) {
        // reduce over the 8 row-groups within the warp (lanes differing in rg)
#pragma unroll
        for (int nt = 0; nt < 4; nt++)
#pragma unroll
            for (int j = 0; j < 2; j++) {
#pragma unroll
                for (int ofs = 4; ofs < 32; ofs <<= 1) {
                    csum[nt][j] += __shfl_xor_sync(0xffffffffu, csum[nt][j], ofs);
                    csq[nt][j]  += __shfl_xor_sync(0xffffffffu, csq[nt][j],  ofs);
                }
            }
        if (rg == 0) {   // lanes 0..3 hold column totals
#pragma unroll
            for (int nt = 0; nt < 4; nt++) {
                int col = wn * 32 + nt * 8 + 2 * q;
                atomicAdd(&s_sum[col],     csum[nt][0]);
                atomicAdd(&s_sum[col + 1], csum[nt][1]);
                atomicAdd(&s_sq[col],      csq[nt][0]);
                atomicAdd(&s_sq[col + 1],  csq[nt][1]);
            }
        }
        __syncthreads();
        if (t < DFEAT) {
            atomicAdd(&g_sum[t], s_sum[t]);
            atomicAdd(&g_sq[t],  s_sq[t]);
        }
    }
}

// ============================================================================
// K4: fold BN stats into affine scale/shift
// ============================================================================
__global__ void finalize_kernel(const float* __restrict__ gamma,
                                const float* __restrict__ beta,
                                float invM)
{
    int t = threadIdx.x;
    float mu   = g_sum[t] * invM;
    float var  = g_sq[t] * invM - mu * mu;
    float rstd = rsqrtf(var + 1e-5f);
    float sc   = rstd * gamma[t];
    g_scale[t] = sc;
    g_shift[t] = beta[t] - mu * sc;
}

// ============================================================================
// launch: resolve inputs by size signature (robust to metadata ordering)
// ============================================================================
extern "C" void kernel_launch(void* const* d_in, const int* in_sizes, int n_in,
                              void* d_out, int out_size)
{
    int ix = -1, ie = -1, iW1 = -1, iW2 = -1, ieps = -1;
    int v128[8]; int n128 = 0;
    long best_x = -1, best_e = -1;
    for (int i = 0; i < n_in; i++) {
        long sz = in_sizes[i];
        if (sz > best_x) {
            best_e = best_x; ie = ix;
            best_x = sz; ix = i;
        } else if (sz > best_e) { best_e = sz; ie = i; }
    }
    for (int i = 0; i < n_in; i++) {
        if (i == ix || i == ie) continue;
        long sz = in_sizes[i];
        if (sz == DFEAT * DFEAT) { if (iW1 < 0) iW1 = i; else iW2 = i; }
        else if (sz == DFEAT)    { if (n128 < 8) v128[n128++] = i; }
        else                     { ieps = i; }
    }
    int ib1, igamma, ibeta, ib2;
    if (ix == 0) { ib1 = v128[0]; igamma = v128[1]; ibeta = v128[2]; ib2 = v128[3]; }
    else         { ib1 = v128[0]; ib2 = v128[1];    ibeta = v128[2]; igamma = v128[3]; }

    const float* x     = (const float*)d_in[ix];
    const void*  ei    = d_in[ie];
    const float* W1    = (const float*)d_in[iW1];
    const float* b1    = (const float*)d_in[ib1];
    const float* gamma = (const float*)d_in[igamma];
    const float* beta  = (const float*)d_in[ibeta];
    const float* W2    = (const float*)d_in[iW2];
    const float* b2    = (const float*)d_in[ib2];
    const float* eps   = (const float*)d_in[ieps];
    float*       out   = (float*)d_out;

    int M = in_sizes[ix] / DFEAT;
    int E = in_sizes[ie] / 2;
    long total4 = (long)M * (DFEAT / 4);

    static int smem_set = 0;
    const int dyn_smem = (BM * SA + 128 * SB) * 4;   // 103,424 bytes -> 2 CTA/SM
    if (!smem_set) {
        cudaFuncSetAttribute(gemm_tc_kernel<1>,
                             cudaFuncAttributeMaxDynamicSharedMemorySize, dyn_smem);
        cudaFuncSetAttribute(gemm_tc_kernel<2>,
                             cudaFuncAttributeMaxDynamicSharedMemorySize, dyn_smem);
        smem_set = 1;
    }

    // K0: detect edge-index dtype
    detect_kernel<<<1, 1>>>((const long long*)ei, E, M);

    // K1: out = (1+eps)*x ; zero stat accumulators
    init_kernel<<<2048, 256>>>((const float4*)x, (float4*)out, eps, total4);

    // K2: out[dst] += x[src]  (GIN sum aggregation)
    scatter_kernel<<<(E + 7) / 8, 256>>>((const float4*)x, ei, (float4*)out, E, M);

    int gblocks = (M + BM - 1) / BM;

    // K3: out = out @ W1 + b1 (in place), BN stats accumulated
    gemm_tc_kernel<1><<<gblocks, 256, dyn_smem>>>(out, W1, b1, M);

    // K4: fold mean/var/gamma/beta into scale/shift
    finalize_kernel<<<1, DFEAT>>>(gamma, beta, 1.0f / (float)M);

    // K5: out = ReLU(BN(out)) @ W2 + b2 (in place)
    gemm_tc_kernel<2><<<gblocks, 256, dyn_smem>>>(out, W2, b2, M);
}

// round 7
// speedup vs baseline: 1.5982x; 1.0092x over previous
#include <cuda_runtime.h>

#define DFEAT 128
#define BM 64
#define SA 136   // A smem stride (words), ≡8 mod 32 -> conflict-free LDS.64 frags
#define SB 136   // B smem stride (words), ≡8 mod 32 -> conflict-free B frags

// ---- persistent device scratch (allocation-free rule) ----
__device__ float g_sum[DFEAT];
__device__ float g_sq[DFEAT];
__device__ float g_scale[DFEAT];
__device__ float g_shift[DFEAT];
__device__ int   g_idx_is64;

__device__ __forceinline__ unsigned f2tf32(float f) {
    unsigned u;
    asm("cvt.rna.tf32.f32 %0, %1;" : "=r"(u) : "f"(f));
    return u;
}

#define MMA_TF32_S(d, a0, a1, a2, a3, b0, b1) \
    asm volatile("mma.sync.aligned.m16n8k8.row.col.f32.tf32.tf32.f32 " \
        "{%0,%1,%2,%3}, {%4,%5,%6,%7}, {%8,%9}, {%0,%1,%2,%3};" \
        : "+f"((d)[0]), "+f"((d)[1]), "+f"((d)[2]), "+f"((d)[3]) \
        : "r"(a0), "r"(a1), "r"(a2), "r"(a3), "r"(b0), "r"(b1))

// ============================================================================
// K0: detect edge-index dtype (int32 vs int64) — parallel, ~1 load round-trip.
// ============================================================================
__global__ void detect_kernel(const long long* __restrict__ ei, int E, int Nnodes)
{
    int t = threadIdx.x;            // 64 threads
    int n = 2 * E < 64 ? 2 * E : 64;
    bool ok = true;
    if (t < n) {
        long long v = ei[t];
        ok = (v >= 0) && (v < (long long)Nnodes);
    }
    unsigned m0 = __ballot_sync(0xffffffffu, ok);
    __shared__ unsigned w[2];
    w[t >> 5] = m0;
    __syncthreads();
    if (t == 0) g_idx_is64 = (w[0] == 0xffffffffu && w[1] == 0xffffffffu) ? 1 : 0;
}

// ============================================================================
// K1: out = (1+eps) * x   (and reset BN stat accumulators)
// ============================================================================
__global__ void init_kernel(const float4* __restrict__ x,
                            float4* __restrict__ out,
                            const float* __restrict__ eps,
                            long total4)
{
    if (blockIdx.x == 0 && threadIdx.x < DFEAT) {
        g_sum[threadIdx.x] = 0.f;
        g_sq[threadIdx.x]  = 0.f;
    }
    float c = 1.0f + *eps;
    long i = (long)blockIdx.x * blockDim.x + threadIdx.x;
    long stride = (long)gridDim.x * blockDim.x;
    for (; i < total4; i += stride) {
        float4 v = x[i];
        v.x *= c; v.y *= c; v.z *= c; v.w *= c;
        out[i] = v;
    }
}

// ============================================================================
// K2: scatter-add  out[dst] += x[src]   (warp per edge, float4 vector atomics)
// ============================================================================
__global__ void scatter_kernel(const float4* __restrict__ x,
                               const void* __restrict__ ei_raw,
                               float4* __restrict__ out,
                               int E, int Nnodes)
{
    int e = blockIdx.x * 8 + (threadIdx.x >> 5);
    if (e >= E) return;
    int lane = threadIdx.x & 31;

    unsigned long long s, d;
    if (g_idx_is64) {
        const long long* ei = (const long long*)ei_raw;
        s = (unsigned long long)ei[e];
        d = (unsigned long long)ei[E + e];
    } else {
        const int* ei = (const int*)ei_raw;
        s = (unsigned long long)(unsigned)ei[e];
        d = (unsigned long long)(unsigned)ei[E + e];
    }
    if (s >= (unsigned long long)Nnodes || d >= (unsigned long long)Nnodes) return;
    float4 v = x[s * 32 + lane];
    atomicAdd(&out[d * 32 + lane], v);   // sm_90+ vector red
}

// ============================================================================
// K3/K5: in-place GEMM via mma.sync tf32.  C[M,128] = f(C) @ W + bias
//   PHASE 1: f = identity; epilogue accumulates per-column sum/sumsq
//   PHASE 2: f = ReLU(BN(.)) applied at A-load via g_scale/g_shift
//
// k-permutation: mma κ-lane q maps to physical k = 2q (and κ=q+4 -> 2q+1),
// per 8-wide k-block. A smem is plain row-major -> each A fragment pair is
// one LDS.64. B smem rows are stored pre-permuted (row σ(k)) so B fragment
// addressing is unchanged and conflict-free. A and B agree on the mapping.
// ============================================================================
template <int PHASE>
__global__ __launch_bounds__(256)
void gemm_tc_kernel(float* __restrict__ C,
                    const float* __restrict__ W,
                    const float* __restrict__ bias,
                    int M)
{
    extern __shared__ unsigned smem_u[];
    unsigned* As = smem_u;                // [64][SA]
    unsigned* Bs = smem_u + BM * SA;      // [128][SB] (k-rows permuted)
    __shared__ float s_scale[DFEAT];
    __shared__ float s_shift[DFEAT];
    __shared__ float s_sum[DFEAT];
    __shared__ float s_sq[DFEAT];

    const int t  = threadIdx.x;
    const int m0 = blockIdx.x * BM;

    if (PHASE == 2) {
        if (t < DFEAT) { s_scale[t] = g_scale[t]; s_shift[t] = g_shift[t]; }
    } else {
        if (t < DFEAT) { s_sum[t] = 0.f; s_sq[t] = 0.f; }
    }
    __syncthreads();

    // ---- load A tile (rows m0..m0+63, all 128 cols), tf32-convert ----
#pragma unroll
    for (int i = 0; i < 8; i++) {
        int idx = i * 256 + t;          // float4 index, 0..2047
        int row = idx >> 5;             // 32 float4 per row
        int c4  = idx & 31;
        float4 v = make_float4(0.f, 0.f, 0.f, 0.f);
        int m = m0 + row;
        if (m < M)
            v = *reinterpret_cast<const float4*>(C + (long)m * DFEAT + c4 * 4);
        if (PHASE == 2) {
            int kb = c4 * 4;
            v.x = fmaxf(fmaf(v.x, s_scale[kb + 0], s_shift[kb + 0]), 0.f);
            v.y = fmaxf(fmaf(v.y, s_scale[kb + 1], s_shift[kb + 1]), 0.f);
            v.z = fmaxf(fmaf(v.z, s_scale[kb + 2], s_shift[kb + 2]), 0.f);
            v.w = fmaxf(fmaf(v.w, s_scale[kb + 3], s_shift[kb + 3]), 0.f);
        }
        uint4 u = make_uint4(f2tf32(v.x), f2tf32(v.y), f2tf32(v.z), f2tf32(v.w));
        *reinterpret_cast<uint4*>(As + row * SA + c4 * 4) = u;
    }
    // ---- load B tile (W[128][128]), tf32-convert, k-rows permuted ----
#pragma unroll
    for (int i = 0; i < 16; i++) {
        int idx = i * 256 + t;
        int k   = idx >> 5;
        int c4  = idx & 31;
        // within each 8-block: phys k=2q -> row q ; phys k=2q+1 -> row q+4
        int nk  = (k & ~7) | ((k & 1) << 2) | ((k & 7) >> 1);
        float4 v = *reinterpret_cast<const float4*>(W + (long)k * DFEAT + c4 * 4);
        uint4 u = make_uint4(f2tf32(v.x), f2tf32(v.y), f2tf32(v.z), f2tf32(v.w));
        *reinterpret_cast<uint4*>(Bs + nk * SB + c4 * 4) = u;
    }
    __syncthreads();

    const int lane = t & 31;
    const int warp = t >> 5;
    const int wm = warp >> 2;      // 0..1
    const int wn = warp & 3;       // 0..3
    const int q  = lane & 3;       // 0..3
    const int rg = lane >> 2;      // 0..7

    float acc[2][4][4];
#pragma unroll
    for (int mt = 0; mt < 2; mt++)
#pragma unroll
        for (int nt = 0; nt < 4; nt++)
#pragma unroll
            for (int j = 0; j < 4; j++) acc[mt][nt][j] = 0.f;

    const unsigned* Abase = As + (wm * 32 + rg) * SA + 2 * q;
    const unsigned* Bbase = Bs + q * SB + wn * 32 + rg;

#pragma unroll
    for (int k0 = 0; k0 < DFEAT; k0 += 8) {
        // A fragments: one LDS.64 per (mt, row-half); κ=q -> .x, κ=q+4 -> .y
        uint2 alo[2], ahi[2];
#pragma unroll
        for (int mt = 0; mt < 2; mt++) {
            alo[mt] = *reinterpret_cast<const uint2*>(Abase + mt * 16 * SA + k0);
            ahi[mt] = *reinterpret_cast<const uint2*>(Abase + (mt * 16 + 8) * SA + k0);
        }
        unsigned b0[4], b1[4];
#pragma unroll
        for (int nt = 0; nt < 4; nt++) {
            b0[nt] = Bbase[k0 * SB + nt * 8];
            b1[nt] = Bbase[(k0 + 4) * SB + nt * 8];
        }
#pragma unroll
        for (int mt = 0; mt < 2; mt++)
#pragma unroll
            for (int nt = 0; nt < 4; nt++)
                MMA_TF32_S(acc[mt][nt],
                           alo[mt].x, ahi[mt].x, alo[mt].y, ahi[mt].y,
                           b0[nt], b1[nt]);
    }

    // ---- epilogue: bias add, in-place store, BN stats (PHASE 1) ----
    float bv[4][2];
#pragma unroll
    for (int nt = 0; nt < 4; nt++) {
        int col = wn * 32 + nt * 8 + 2 * q;
        bv[nt][0] = bias[col];
        bv[nt][1] = bias[col + 1];
    }

    float csum[4][2], csq[4][2];
#pragma unroll
    for (int nt = 0; nt < 4; nt++) {
        csum[nt][0] = csum[nt][1] = 0.f;
        csq[nt][0]  = csq[nt][1]  = 0.f;
    }

#pragma unroll
    for (int mt = 0; mt < 2; mt++) {
        int r0 = m0 + wm * 32 + mt * 16 + rg;
        int r1 = r0 + 8;
#pragma unroll
        for (int nt = 0; nt < 4; nt++) {
            int col = wn * 32 + nt * 8 + 2 * q;
            float v0 = acc[mt][nt][0] + bv[nt][0];
            float v1 = acc[mt][nt][1] + bv[nt][1];
            float v2 = acc[mt][nt][2] + bv[nt][0];
            float v3 = acc[mt][nt][3] + bv[nt][1];
            if (r0 < M) {
                *reinterpret_cast<float2*>(C + (long)r0 * DFEAT + col) =
                    make_float2(v0, v1);
                if (PHASE == 1) {
                    csum[nt][0] += v0; csq[nt][0] += v0 * v0;
                    csum[nt][1] += v1; csq[nt][1] += v1 * v1;
                }
            }
            if (r1 < M) {
                *reinterpret_cast<float2*>(C + (long)r1 * DFEAT + col) =
                    make_float2(v2, v3);
                if (PHASE == 1) {
                    csum[nt][0] += v2; csq[nt][0] += v2 * v2;
                    csum[nt][1] += v3; csq[nt][1] += v3 * v3;
                }
            }
        }
    }

    if (PHASE == 1) {
        // reduce over the 8 row-groups within the warp (lanes differing in rg)
#pragma unroll
        for (int nt = 0; nt < 4; nt++)
#pragma unroll
            for (int j = 0; j < 2; j++) {
#pragma unroll
                for (int ofs = 4; ofs < 32; ofs <<= 1) {
                    csum[nt][j] += __shfl_xor_sync(0xffffffffu, csum[nt][j], ofs);
                    csq[nt][j]  += __shfl_xor_sync(0xffffffffu, csq[nt][j],  ofs);
                }
            }
        if (rg == 0) {   // lanes 0..3 hold column totals
#pragma unroll
            for (int nt = 0; nt < 4; nt++) {
                int col = wn * 32 + nt * 8 + 2 * q;
                atomicAdd(&s_sum[col],     csum[nt][0]);
                atomicAdd(&s_sum[col + 1], csum[nt][1]);
                atomicAdd(&s_sq[col],      csq[nt][0]);
                atomicAdd(&s_sq[col + 1],  csq[nt][1]);
            }
        }
        __syncthreads();
        if (t < DFEAT) {
            atomicAdd(&g_sum[t], s_sum[t]);
            atomicAdd(&g_sq[t],  s_sq[t]);
        }
    }
}

// ============================================================================
// K4: fold BN stats into affine scale/shift
// ============================================================================
__global__ void finalize_kernel(const float* __restrict__ gamma,
                                const float* __restrict__ beta,
                                float invM)
{
    int t = threadIdx.x;
    float mu   = g_sum[t] * invM;
    float var  = g_sq[t] * invM - mu * mu;
    float rstd = rsqrtf(var + 1e-5f);
    float sc   = rstd * gamma[t];
    g_scale[t] = sc;
    g_shift[t] = beta[t] - mu * sc;
}

// ============================================================================
// launch: resolve inputs by size signature (robust to metadata ordering)
// ============================================================================
extern "C" void kernel_launch(void* const* d_in, const int* in_sizes, int n_in,
                              void* d_out, int out_size)
{
    int ix = -1, ie = -1, iW1 = -1, iW2 = -1, ieps = -1;
    int v128[8]; int n128 = 0;
    long best_x = -1, best_e = -1;
    for (int i = 0; i < n_in; i++) {
        long sz = in_sizes[i];
        if (sz > best_x) {
            best_e = best_x; ie = ix;
            best_x = sz; ix = i;
        } else if (sz > best_e) { best_e = sz; ie = i; }
    }
    for (int i = 0; i < n_in; i++) {
        if (i == ix || i == ie) continue;
        long sz = in_sizes[i];
        if (sz == DFEAT * DFEAT) { if (iW1 < 0) iW1 = i; else iW2 = i; }
        else if (sz == DFEAT)    { if (n128 < 8) v128[n128++] = i; }
        else                     { ieps = i; }
    }
    int ib1, igamma, ibeta, ib2;
    if (ix == 0) { ib1 = v128[0]; igamma = v128[1]; ibeta = v128[2]; ib2 = v128[3]; }
    else         { ib1 = v128[0]; ib2 = v128[1];    ibeta = v128[2]; igamma = v128[3]; }

    const float* x     = (const float*)d_in[ix];
    const void*  ei    = d_in[ie];
    const float* W1    = (const float*)d_in[iW1];
    const float* b1    = (const float*)d_in[ib1];
    const float* gamma = (const float*)d_in[igamma];
    const float* beta  = (const float*)d_in[ibeta];
    const float* W2    = (const float*)d_in[iW2];
    const float* b2    = (const float*)d_in[ib2];
    const float* eps   = (const float*)d_in[ieps];
    float*       out   = (float*)d_out;

    int M = in_sizes[ix] / DFEAT;
    int E = in_sizes[ie] / 2;
    long total4 = (long)M * (DFEAT / 4);

    static int smem_set = 0;
    const int dyn_smem = (BM * SA + 128 * SB) * 4;   // 104,448 bytes -> 2 CTA/SM
    if (!smem_set) {
        cudaFuncSetAttribute(gemm_tc_kernel<1>,
                             cudaFuncAttributeMaxDynamicSharedMemorySize, dyn_smem);
        cudaFuncSetAttribute(gemm_tc_kernel<2>,
                             cudaFuncAttributeMaxDynamicSharedMemorySize, dyn_smem);
        smem_set = 1;
    }

    // K0: detect edge-index dtype (parallel)
    detect_kernel<<<1, 64>>>((const long long*)ei, E, M);

    // K1: out = (1+eps)*x ; zero stat accumulators
    init_kernel<<<2048, 256>>>((const float4*)x, (float4*)out, eps, total4);

    // K2: out[dst] += x[src]  (GIN sum aggregation)
    scatter_kernel<<<(E + 7) / 8, 256>>>((const float4*)x, ei, (float4*)out, E, M);

    int gblocks = (M + BM - 1) / BM;

    // K3: out = out @ W1 + b1 (in place), BN stats accumulated
    gemm_tc_kernel<1><<<gblocks, 256, dyn_smem>>>(out, W1, b1, M);

    // K4: fold mean/var/gamma/beta into scale/shift
    finalize_kernel<<<1, DFEAT>>>(gamma, beta, 1.0f / (float)M);

    // K5: out = ReLU(BN(out)) @ W2 + b2 (in place)
    gemm_tc_kernel<2><<<gblocks, 256, dyn_smem>>>(out, W2, b2, M);
}

// round 8
// speedup vs baseline: 1.7323x; 1.0839x over previous
#include <cuda_runtime.h>

#define DFEAT 128
#define BM 64
#define SA 136   // A smem stride (words), ≡8 mod 32 -> conflict-free LDS.64 frags
#define SB 136   // B smem stride (words), ≡8 mod 32 -> conflict-free B frags

// ---- persistent device scratch (allocation-free rule) ----
__device__ float g_sum[DFEAT];
__device__ float g_sq[DFEAT];
__device__ float g_scale[DFEAT];
__device__ float g_shift[DFEAT];
__device__ int   g_idx_is64;

__device__ __forceinline__ unsigned f2tf32(float f) {
    unsigned u;
    asm("cvt.rna.tf32.f32 %0, %1;" : "=r"(u) : "f"(f));
    return u;
}

#define MMA_TF32_S(d, a0, a1, a2, a3, b0, b1) \
    asm volatile("mma.sync.aligned.m16n8k8.row.col.f32.tf32.tf32.f32 " \
        "{%0,%1,%2,%3}, {%4,%5,%6,%7}, {%8,%9}, {%0,%1,%2,%3};" \
        : "+f"((d)[0]), "+f"((d)[1]), "+f"((d)[2]), "+f"((d)[3]) \
        : "r"(a0), "r"(a1), "r"(a2), "r"(a3), "r"(b0), "r"(b1))

// ============================================================================
// K0: detect edge-index dtype (int32 vs int64) — parallel.
// ============================================================================
__global__ void detect_kernel(const long long* __restrict__ ei, int E, int Nnodes)
{
    int t = threadIdx.x;            // 64 threads
    int n = 2 * E < 64 ? 2 * E : 64;
    bool ok = true;
    if (t < n) {
        long long v = ei[t];
        ok = (v >= 0) && (v < (long long)Nnodes);
    }
    unsigned m0 = __ballot_sync(0xffffffffu, ok);
    __shared__ unsigned w[2];
    w[t >> 5] = m0;
    __syncthreads();
    if (t == 0) g_idx_is64 = (w[0] == 0xffffffffu && w[1] == 0xffffffffu) ? 1 : 0;
}

// ============================================================================
// K1: out = (1+eps) * x   (and reset BN stat accumulators)
// ============================================================================
__global__ void init_kernel(const float4* __restrict__ x,
                            float4* __restrict__ out,
                            const float* __restrict__ eps,
                            long total4)
{
    if (blockIdx.x == 0 && threadIdx.x < DFEAT) {
        g_sum[threadIdx.x] = 0.f;
        g_sq[threadIdx.x]  = 0.f;
    }
    float c = 1.0f + *eps;
    long i = (long)blockIdx.x * blockDim.x + threadIdx.x;
    long stride = (long)gridDim.x * blockDim.x;
    for (; i < total4; i += stride) {
        float4 v = x[i];
        v.x *= c; v.y *= c; v.z *= c; v.w *= c;
        out[i] = v;
    }
}

// ============================================================================
// K2: scatter-add  out[dst] += x[src]   (warp per edge, float4 vector atomics)
// ============================================================================
__global__ void scatter_kernel(const float4* __restrict__ x,
                               const void* __restrict__ ei_raw,
                               float4* __restrict__ out,
                               int E, int Nnodes)
{
    int e = blockIdx.x * 8 + (threadIdx.x >> 5);
    if (e >= E) return;
    int lane = threadIdx.x & 31;

    unsigned long long s, d;
    if (g_idx_is64) {
        const long long* ei = (const long long*)ei_raw;
        s = (unsigned long long)ei[e];
        d = (unsigned long long)ei[E + e];
    } else {
        const int* ei = (const int*)ei_raw;
        s = (unsigned long long)(unsigned)ei[e];
        d = (unsigned long long)(unsigned)ei[E + e];
    }
    if (s >= (unsigned long long)Nnodes || d >= (unsigned long long)Nnodes) return;
    float4 v = x[s * 32 + lane];
    atomicAdd(&out[d * 32 + lane], v);   // sm_90+ vector red
}

// ============================================================================
// K3/K5: PERSISTENT in-place GEMM via mma.sync tf32.  C[M,128]=f(C)@W+bias
//   - B (W) loaded to smem ONCE per CTA, reused across all tiles.
//   - next tile's A prefetched into registers during current tile's MMA.
//   - PHASE 1: BN sum/sumsq accumulated in regs across tiles, flushed once.
//   - PHASE 2: ReLU(BN(.)) applied at A store-to-smem.
// k-permutation (κ=q -> 2q, κ=q+4 -> 2q+1 per 8-block): A frags are LDS.64,
// B rows stored pre-permuted so B addressing is unchanged.
// ============================================================================
template <int PHASE>
__global__ __launch_bounds__(256, 2)
void gemm_tc_kernel(float* __restrict__ C,
                    const float* __restrict__ W,
                    const float* __restrict__ bias,
                    int M, int ntiles)
{
    extern __shared__ unsigned smem_u[];
    unsigned* As = smem_u;                // [64][SA]
    unsigned* Bs = smem_u + BM * SA;      // [128][SB] (k-rows permuted)
    __shared__ float s_scale[DFEAT];
    __shared__ float s_shift[DFEAT];

    const int t    = threadIdx.x;
    const int lane = t & 31;
    const int warp = t >> 5;

    // ---- prefetch first A tile into registers (rows: i*8+warp, col4: lane) ----
    int tile = blockIdx.x;
    float4 areg[8];
    if (tile < ntiles) {
#pragma unroll
        for (int i = 0; i < 8; i++) {
            int m = tile * BM + i * 8 + warp;
            areg[i] = (m < M)
                ? *reinterpret_cast<const float4*>(C + (long)m * DFEAT + lane * 4)
                : make_float4(0.f, 0.f, 0.f, 0.f);
        }
    }

    if (PHASE == 2) {
        if (t < DFEAT) { s_scale[t] = g_scale[t]; s_shift[t] = g_shift[t]; }
    }

    // ---- load B tile ONCE (W[128][128]), tf32-convert, k-rows permuted ----
#pragma unroll
    for (int i = 0; i < 16; i++) {
        int k  = i * 8 + warp;
        int nk = (k & ~7) | ((k & 1) << 2) | ((k & 7) >> 1);
        float4 v = *reinterpret_cast<const float4*>(W + (long)k * DFEAT + lane * 4);
        uint4 u = make_uint4(f2tf32(v.x), f2tf32(v.y), f2tf32(v.z), f2tf32(v.w));
        *reinterpret_cast<uint4*>(Bs + nk * SB + lane * 4) = u;
    }

    const int wm = warp >> 2;      // 0..1
    const int wn = warp & 3;       // 0..3
    const int q  = lane & 3;       // 0..3
    const int rg = lane >> 2;      // 0..7

    float bv[4][2];
#pragma unroll
    for (int nt = 0; nt < 4; nt++) {
        int col = wn * 32 + nt * 8 + 2 * q;
        bv[nt][0] = bias[col];
        bv[nt][1] = bias[col + 1];
    }

    float csum[4][2] = {{0.f,0.f},{0.f,0.f},{0.f,0.f},{0.f,0.f}};
    float csq [4][2] = {{0.f,0.f},{0.f,0.f},{0.f,0.f},{0.f,0.f}};

    const unsigned* Abase = As + (wm * 32 + rg) * SA + 2 * q;
    const unsigned* Bbase = Bs + q * SB + wn * 32 + rg;
    unsigned* Asts = As + warp * SA + lane * 4;   // + i*8*SA per chunk

    __syncthreads();   // B (and s_scale) ready

    while (tile < ntiles) {
        // ---- store current A tile to smem (with PHASE-2 transform) ----
#pragma unroll
        for (int i = 0; i < 8; i++) {
            float4 v = areg[i];
            if (PHASE == 2) {
                int kb = lane * 4;
                v.x = fmaxf(fmaf(v.x, s_scale[kb + 0], s_shift[kb + 0]), 0.f);
                v.y = fmaxf(fmaf(v.y, s_scale[kb + 1], s_shift[kb + 1]), 0.f);
                v.z = fmaxf(fmaf(v.z, s_scale[kb + 2], s_shift[kb + 2]), 0.f);
                v.w = fmaxf(fmaf(v.w, s_scale[kb + 3], s_shift[kb + 3]), 0.f);
            }
            uint4 u = make_uint4(f2tf32(v.x), f2tf32(v.y), f2tf32(v.z), f2tf32(v.w));
            *reinterpret_cast<uint4*>(Asts + i * 8 * SA) = u;
        }
        __syncthreads();

        // ---- prefetch next tile's A (overlaps the MMAs below) ----
        int next = tile + gridDim.x;
        if (next < ntiles) {
#pragma unroll
            for (int i = 0; i < 8; i++) {
                int m = next * BM + i * 8 + warp;
                areg[i] = (m < M)
                    ? *reinterpret_cast<const float4*>(C + (long)m * DFEAT + lane * 4)
                    : make_float4(0.f, 0.f, 0.f, 0.f);
            }
        }

        // ---- MMAs over K=128 ----
        float acc[2][4][4];
#pragma unroll
        for (int mt = 0; mt < 2; mt++)
#pragma unroll
            for (int nt = 0; nt < 4; nt++)
#pragma unroll
                for (int j = 0; j < 4; j++) acc[mt][nt][j] = 0.f;

#pragma unroll
        for (int k0 = 0; k0 < DFEAT; k0 += 8) {
            uint2 alo[2], ahi[2];
#pragma unroll
            for (int mt = 0; mt < 2; mt++) {
                alo[mt] = *reinterpret_cast<const uint2*>(Abase + mt * 16 * SA + k0);
                ahi[mt] = *reinterpret_cast<const uint2*>(Abase + (mt * 16 + 8) * SA + k0);
            }
            unsigned b0[4], b1[4];
#pragma unroll
            for (int nt = 0; nt < 4; nt++) {
                b0[nt] = Bbase[k0 * SB + nt * 8];
                b1[nt] = Bbase[(k0 + 4) * SB + nt * 8];
            }
#pragma unroll
            for (int mt = 0; mt < 2; mt++)
#pragma unroll
                for (int nt = 0; nt < 4; nt++)
                    MMA_TF32_S(acc[mt][nt],
                               alo[mt].x, ahi[mt].x, alo[mt].y, ahi[mt].y,
                               b0[nt], b1[nt]);
        }
        __syncthreads();   // all warps done reading As -> next STS is safe

        // ---- epilogue: bias add, in-place store, BN stat accumulation ----
        int mb = tile * BM;
#pragma unroll
        for (int mt = 0; mt < 2; mt++) {
            int r0 = mb + wm * 32 + mt * 16 + rg;
            int r1 = r0 + 8;
#pragma unroll
            for (int nt = 0; nt < 4; nt++) {
                int col = wn * 32 + nt * 8 + 2 * q;
                float v0 = acc[mt][nt][0] + bv[nt][0];
                float v1 = acc[mt][nt][1] + bv[nt][1];
                float v2 = acc[mt][nt][2] + bv[nt][0];
                float v3 = acc[mt][nt][3] + bv[nt][1];
                if (r0 < M) {
                    *reinterpret_cast<float2*>(C + (long)r0 * DFEAT + col) =
                        make_float2(v0, v1);
                    if (PHASE == 1) {
                        csum[nt][0] += v0; csq[nt][0] += v0 * v0;
                        csum[nt][1] += v1; csq[nt][1] += v1 * v1;
                    }
                }
                if (r1 < M) {
                    *reinterpret_cast<float2*>(C + (long)r1 * DFEAT + col) =
                        make_float2(v2, v3);
                    if (PHASE == 1) {
                        csum[nt][0] += v2; csq[nt][0] += v2 * v2;
                        csum[nt][1] += v3; csq[nt][1] += v3 * v3;
                    }
                }
            }
        }
        tile = next;
    }

    if (PHASE == 1) {
        // one flush per CTA: reduce over rg lanes, atomics from rg==0
#pragma unroll
        for (int nt = 0; nt < 4; nt++)
#pragma unroll
            for (int j = 0; j < 2; j++) {
#pragma unroll
                for (int ofs = 4; ofs < 32; ofs <<= 1) {
                    csum[nt][j] += __shfl_xor_sync(0xffffffffu, csum[nt][j], ofs);
                    csq[nt][j]  += __shfl_xor_sync(0xffffffffu, csq[nt][j],  ofs);
                }
            }
        if (rg == 0) {
#pragma unroll
            for (int nt = 0; nt < 4; nt++) {
                int col = wn * 32 + nt * 8 + 2 * q;
                atomicAdd(&g_sum[col],     csum[nt][0]);
                atomicAdd(&g_sum[col + 1], csum[nt][1]);
                atomicAdd(&g_sq[col],      csq[nt][0]);
                atomicAdd(&g_sq[col + 1],  csq[nt][1]);
            }
        }
    }
}

// ============================================================================
// K4: fold BN stats into affine scale/shift
// ============================================================================
__global__ void finalize_kernel(const float* __restrict__ gamma,
                                const float* __restrict__ beta,
                                float invM)
{
    int t = threadIdx.x;
    float mu   = g_sum[t] * invM;
    float var  = g_sq[t] * invM - mu * mu;
    float rstd = rsqrtf(var + 1e-5f);
    float sc   = rstd * gamma[t];
    g_scale[t] = sc;
    g_shift[t] = beta[t] - mu * sc;
}

// ============================================================================
// launch: resolve inputs by size signature (robust to metadata ordering)
// ============================================================================
extern "C" void kernel_launch(void* const* d_in, const int* in_sizes, int n_in,
                              void* d_out, int out_size)
{
    int ix = -1, ie = -1, iW1 = -1, iW2 = -1, ieps = -1;
    int v128[8]; int n128 = 0;
    long best_x = -1, best_e = -1;
    for (int i = 0; i < n_in; i++) {
        long sz = in_sizes[i];
        if (sz > best_x) {
            best_e = best_x; ie = ix;
            best_x = sz; ix = i;
        } else if (sz > best_e) { best_e = sz; ie = i; }
    }
    for (int i = 0; i < n_in; i++) {
        if (i == ix || i == ie) continue;
        long sz = in_sizes[i];
        if (sz == DFEAT * DFEAT) { if (iW1 < 0) iW1 = i; else iW2 = i; }
        else if (sz == DFEAT)    { if (n128 < 8) v128[n128++] = i; }
        else                     { ieps = i; }
    }
    int ib1, igamma, ibeta, ib2;
    if (ix == 0) { ib1 = v128[0]; igamma = v128[1]; ibeta = v128[2]; ib2 = v128[3]; }
    else         { ib1 = v128[0]; ib2 = v128[1];    ibeta = v128[2]; igamma = v128[3]; }

    const float* x     = (const float*)d_in[ix];
    const void*  ei    = d_in[ie];
    const float* W1    = (const float*)d_in[iW1];
    const float* b1    = (const float*)d_in[ib1];
    const float* gamma = (const float*)d_in[igamma];
    const float* beta  = (const float*)d_in[ibeta];
    const float* W2    = (const float*)d_in[iW2];
    const float* b2    = (const float*)d_in[ib2];
    const float* eps   = (const float*)d_in[ieps];
    float*       out   = (float*)d_out;

    int M = in_sizes[ix] / DFEAT;
    int E = in_sizes[ie] / 2;
    long total4 = (long)M * (DFEAT / 4);

    static int nsm = 0;
    const int dyn_smem = (BM * SA + 128 * SB) * 4;   // 104,448 B -> 2 CTA/SM
    if (!nsm) {
        cudaFuncSetAttribute(gemm_tc_kernel<1>,
                             cudaFuncAttributeMaxDynamicSharedMemorySize, dyn_smem);
        cudaFuncSetAttribute(gemm_tc_kernel<2>,
                             cudaFuncAttributeMaxDynamicSharedMemorySize, dyn_smem);
        cudaDeviceGetAttribute(&nsm, cudaDevAttrMultiProcessorCount, 0);
        if (nsm <= 0) nsm = 148;
    }

    // K0: detect edge-index dtype (parallel)
    detect_kernel<<<1, 64>>>((const long long*)ei, E, M);

    // K1: out = (1+eps)*x ; zero stat accumulators
    init_kernel<<<2048, 256>>>((const float4*)x, (float4*)out, eps, total4);

    // K2: out[dst] += x[src]  (GIN sum aggregation)
    scatter_kernel<<<(E + 7) / 8, 256>>>((const float4*)x, ei, (float4*)out, E, M);

    int ntiles = (M + BM - 1) / BM;
    int pgrid  = 2 * nsm;
    if (pgrid > ntiles) pgrid = ntiles;

    // K3: out = out @ W1 + b1 (in place, persistent), BN stats accumulated
    gemm_tc_kernel<1><<<pgrid, 256, dyn_smem>>>(out, W1, b1, M, ntiles);

    // K4: fold mean/var/gamma/beta into scale/shift
    finalize_kernel<<<1, DFEAT>>>(gamma, beta, 1.0f / (float)M);

    // K5: out = ReLU(BN(out)) @ W2 + b2 (in place, persistent)
    gemm_tc_kernel<2><<<pgrid, 256, dyn_smem>>>(out, W2, b2, M, ntiles);
}